// round 5
// baseline (speedup 1.0000x reference)
#include <cuda_runtime.h>
#include <cstdint>
#include <cstddef>

#define B_  2048
#define T_  256
#define D_  42
#define H_  64
#define HP  20          // h smem pitch in floats (quad-bank-conflict-free for float4)

// 512MB scratch: gate-packed layer-0 preactivations, float4 (i,f,g,o) per (t,b,j)
__device__ float4 g_gx0[(size_t)B_ * T_ * H_];

__device__ __forceinline__ float sigf(float x)  { return __fdividef(1.0f, 1.0f + __expf(-x)); }
__device__ __forceinline__ float tanhf_(float x){ float e = __expf(2.0f * x); return 1.0f - __fdividef(2.0f, e + 1.0f); }

// ============================================================================
// Prepass: gx0[t][b][j] = (i,f,g,o) = x[b,t,:] . W_ih0[g*64+j,:] + b_ih0 + b_hh0
// One block = 16 consecutive (b,t) rows; 256 threads = 4 row-slots x 64 units.
// ============================================================================
__global__ void __launch_bounds__(256)
gx0_prepass(const float* __restrict__ x,
            const float* __restrict__ Wih0,
            const float* __restrict__ bih0,
            const float* __restrict__ bhh0)
{
    __shared__ float4 Wsh[D_ * H_];   // [d][j] gate-packed, 43008 B
    __shared__ float4 bsh[H_];        // 1024 B
    __shared__ float  xsh[16 * D_];   // 2688 B

    const int tid  = threadIdx.x;
    const int j    = tid & 63;
    const int slot = tid >> 6;        // 0..3, each handles 4 rows

    for (int idx = tid; idx < D_ * H_; idx += 256) {
        int d = idx >> 6, jj = idx & 63;
        Wsh[idx] = make_float4(Wih0[(jj      ) * D_ + d],
                               Wih0[(jj +  64) * D_ + d],
                               Wih0[(jj + 128) * D_ + d],
                               Wih0[(jj + 192) * D_ + d]);
    }
    if (tid < 64) {
        bsh[tid] = make_float4(bih0[tid      ] + bhh0[tid      ],
                               bih0[tid +  64] + bhh0[tid +  64],
                               bih0[tid + 128] + bhh0[tid + 128],
                               bih0[tid + 192] + bhh0[tid + 192]);
    }
    const size_t bt0 = (size_t)blockIdx.x * 16;
    for (int idx = tid; idx < 16 * D_; idx += 256) {
        int r = idx / D_, d = idx - r * D_;
        xsh[idx] = x[(bt0 + r) * D_ + d];
    }
    __syncthreads();

    float4 acc[4];
    const float4 bj = bsh[j];
    #pragma unroll
    for (int r = 0; r < 4; r++) acc[r] = bj;

    #pragma unroll 6
    for (int d = 0; d < D_; d++) {
        float4 w = Wsh[d * 64 + j];
        #pragma unroll
        for (int r = 0; r < 4; r++) {
            float xv = xsh[(slot * 4 + r) * D_ + d];
            acc[r].x += w.x * xv;
            acc[r].y += w.y * xv;
            acc[r].z += w.z * xv;
            acc[r].w += w.w * xv;
        }
    }
    #pragma unroll
    for (int r = 0; r < 4; r++) {
        size_t bt = bt0 + slot * 4 + r;
        size_t b  = bt / T_;
        size_t t  = bt - b * T_;
        g_gx0[(t * B_ + b) * H_ + j] = acc[r];
    }
}

// ============================================================================
// Recurrent kernel: 128 blocks x 16 rows, 256 threads.
// Thread (j = tid&63, rq = tid>>6) owns hidden unit j for rows rq*4..rq*4+3.
// ============================================================================
#define SMEM_REC (3 * 64 * 64 * 16 + 64 * 16 + 2 * 64 * HP * 4)  // 207872 B

__global__ void __launch_bounds__(256, 1)
lstm_rec(const float* __restrict__ Whh0,
         const float* __restrict__ Wih1,
         const float* __restrict__ Whh1,
         const float* __restrict__ bih1,
         const float* __restrict__ bhh1,
         const float* __restrict__ Wfc,
         const float* __restrict__ bfc,
         float* __restrict__ out)
{
    extern __shared__ char sm[];
    float4* W0  = (float4*)sm;            // [k*64 + j], gate-packed, 64KB
    float4* W1i = W0  + 64 * 64;          // 64KB
    float4* W1h = W1i + 64 * 64;          // 64KB
    float4* b1  = W1h + 64 * 64;          // 64 entries
    float*  h0s = (float*)(b1 + 64);      // [j*HP + row], 5120B
    float*  h1s = h0s + 64 * HP;          // 5120B

    const int tid  = threadIdx.x;
    const int j    = tid & 63;
    const int rq   = tid >> 6;            // 0..3
    const int base = blockIdx.x * 16;
    const int ro   = rq * 4;              // first of this thread's 4 rows

    // Gate-pack weights into smem: entry [k][j] = (W[0*64+j][k], W[64+j][k], ...)
    for (int idx = tid; idx < 64 * 64; idx += 256) {
        int k = idx >> 6, jj = idx & 63;
        W0[idx]  = make_float4(Whh0[(jj      ) * 64 + k], Whh0[(jj +  64) * 64 + k],
                               Whh0[(jj + 128) * 64 + k], Whh0[(jj + 192) * 64 + k]);
        W1i[idx] = make_float4(Wih1[(jj      ) * 64 + k], Wih1[(jj +  64) * 64 + k],
                               Wih1[(jj + 128) * 64 + k], Wih1[(jj + 192) * 64 + k]);
        W1h[idx] = make_float4(Whh1[(jj      ) * 64 + k], Whh1[(jj +  64) * 64 + k],
                               Whh1[(jj + 128) * 64 + k], Whh1[(jj + 192) * 64 + k]);
    }
    if (tid < 64) {
        b1[tid] = make_float4(bih1[tid      ] + bhh1[tid      ],
                              bih1[tid +  64] + bhh1[tid +  64],
                              bih1[tid + 128] + bhh1[tid + 128],
                              bih1[tid + 192] + bhh1[tid + 192]);
    }
    for (int idx = tid; idx < 64 * HP; idx += 256) { h0s[idx] = 0.0f; h1s[idx] = 0.0f; }
    __syncthreads();

    float c0[4] = {0.f, 0.f, 0.f, 0.f};
    float c1[4] = {0.f, 0.f, 0.f, 0.f};

    // prefetch t = 0
    float4 gx[4];
    #pragma unroll
    for (int r = 0; r < 4; r++)
        gx[r] = g_gx0[((size_t)0 * B_ + base + ro + r) * H_ + j];

    for (int t = 0; t < T_; t++) {
        // prefetch next step's gx0 (hides DRAM latency behind the matvecs)
        float4 gxn[4];
        if (t + 1 < T_) {
            #pragma unroll
            for (int r = 0; r < 4; r++)
                gxn[r] = g_gx0[((size_t)(t + 1) * B_ + base + ro + r) * H_ + j];
        }

        // ---------------- layer 0: gates = gx0 + W_hh0 . h0_prev ----------------
        float4 a0 = gx[0], a1_ = gx[1], a2 = gx[2], a3 = gx[3];
        #pragma unroll 8
        for (int k = 0; k < 64; k++) {
            float4 w  = W0[k * 64 + j];                        // lane-contiguous LDS.128
            float4 hv = *(const float4*)&h0s[k * HP + ro];     // warp-uniform broadcast
            a0.x += w.x * hv.x; a0.y += w.y * hv.x; a0.z += w.z * hv.x; a0.w += w.w * hv.x;
            a1_.x += w.x * hv.y; a1_.y += w.y * hv.y; a1_.z += w.z * hv.y; a1_.w += w.w * hv.y;
            a2.x += w.x * hv.z; a2.y += w.y * hv.z; a2.z += w.z * hv.z; a2.w += w.w * hv.z;
            a3.x += w.x * hv.w; a3.y += w.y * hv.w; a3.z += w.z * hv.w; a3.w += w.w * hv.w;
        }
        float h0n[4];
        {
            float4 A[4] = {a0, a1_, a2, a3};
            #pragma unroll
            for (int r = 0; r < 4; r++) {
                float i_ = sigf(A[r].x), f_ = sigf(A[r].y);
                float g_ = tanhf_(A[r].z), o_ = sigf(A[r].w);
                c0[r]  = f_ * c0[r] + i_ * g_;
                h0n[r] = o_ * tanhf_(c0[r]);
            }
        }
        __syncthreads();   // all reads of old h0 done
        *(float4*)&h0s[j * HP + ro] = make_float4(h0n[0], h0n[1], h0n[2], h0n[3]);
        __syncthreads();   // new h0 visible

        // -------- layer 1: gates = b1 + W_ih1 . h0_new + W_hh1 . h1_prev --------
        float4 B0, B1, B2, B3;
        {
            float4 bj = b1[j];
            B0 = bj; B1 = bj; B2 = bj; B3 = bj;
        }
        #pragma unroll 4
        for (int k = 0; k < 64; k++) {
            float4 wi  = W1i[k * 64 + j];
            float4 wh  = W1h[k * 64 + j];
            float4 h0v = *(const float4*)&h0s[k * HP + ro];
            float4 h1v = *(const float4*)&h1s[k * HP + ro];
            B0.x += wi.x * h0v.x; B0.y += wi.y * h0v.x; B0.z += wi.z * h0v.x; B0.w += wi.w * h0v.x;
            B1.x += wi.x * h0v.y; B1.y += wi.y * h0v.y; B1.z += wi.z * h0v.y; B1.w += wi.w * h0v.y;
            B2.x += wi.x * h0v.z; B2.y += wi.y * h0v.z; B2.z += wi.z * h0v.z; B2.w += wi.w * h0v.z;
            B3.x += wi.x * h0v.w; B3.y += wi.y * h0v.w; B3.z += wi.z * h0v.w; B3.w += wi.w * h0v.w;
            B0.x += wh.x * h1v.x; B0.y += wh.y * h1v.x; B0.z += wh.z * h1v.x; B0.w += wh.w * h1v.x;
            B1.x += wh.x * h1v.y; B1.y += wh.y * h1v.y; B1.z += wh.z * h1v.y; B1.w += wh.w * h1v.y;
            B2.x += wh.x * h1v.z; B2.y += wh.y * h1v.z; B2.z += wh.z * h1v.z; B2.w += wh.w * h1v.z;
            B3.x += wh.x * h1v.w; B3.y += wh.y * h1v.w; B3.z += wh.z * h1v.w; B3.w += wh.w * h1v.w;
        }
        float h1n[4];
        {
            float4 A[4] = {B0, B1, B2, B3};
            #pragma unroll
            for (int r = 0; r < 4; r++) {
                float i_ = sigf(A[r].x), f_ = sigf(A[r].y);
                float g_ = tanhf_(A[r].z), o_ = sigf(A[r].w);
                c1[r]  = f_ * c1[r] + i_ * g_;
                h1n[r] = o_ * tanhf_(c1[r]);
            }
        }
        __syncthreads();   // all reads of old h1 done
        *(float4*)&h1s[j * HP + ro] = make_float4(h1n[0], h1n[1], h1n[2], h1n[3]);
        __syncthreads();   // new h1 visible

        if (t + 1 < T_) {
            #pragma unroll
            for (int r = 0; r < 4; r++) gx[r] = gxn[r];
        }
    }

    // ---------------- fc (64 -> 5) + softmax on final h1 ----------------
    if (tid < 16) {
        const int row = tid;
        const int b   = base + row;
        float lg[5];
        float mx = -1e30f;
        #pragma unroll
        for (int o = 0; o < 5; o++) {
            float s = bfc[o];
            #pragma unroll 8
            for (int k = 0; k < 64; k++)
                s += h1s[k * HP + row] * Wfc[o * 64 + k];
            lg[o] = s;
            mx = fmaxf(mx, s);
        }
        float e[5], den = 0.0f;
        #pragma unroll
        for (int o = 0; o < 5; o++) { e[o] = __expf(lg[o] - mx); den += e[o]; }
        float inv = __fdividef(1.0f, den);
        #pragma unroll
        for (int o = 0; o < 5; o++) out[(size_t)b * 5 + o] = e[o] * inv;
    }
}

// ============================================================================
extern "C" void kernel_launch(void* const* d_in, const int* in_sizes, int n_in,
                              void* d_out, int out_size)
{
    const float* x    = (const float*)d_in[0];
    const float* Wih0 = (const float*)d_in[1];
    const float* Whh0 = (const float*)d_in[2];
    const float* bih0 = (const float*)d_in[3];
    const float* bhh0 = (const float*)d_in[4];
    const float* Wih1 = (const float*)d_in[5];
    const float* Whh1 = (const float*)d_in[6];
    const float* bih1 = (const float*)d_in[7];
    const float* bhh1 = (const float*)d_in[8];
    const float* Wfc  = (const float*)d_in[9];
    const float* bfc  = (const float*)d_in[10];
    float* out = (float*)d_out;

    cudaFuncSetAttribute(lstm_rec, cudaFuncAttributeMaxDynamicSharedMemorySize, SMEM_REC);

    gx0_prepass<<<(B_ * T_) / 16, 256>>>(x, Wih0, bih0, bhh0);
    lstm_rec<<<B_ / 16, 256, SMEM_REC>>>(Whh0, Wih1, Whh1, bih1, bhh1, Wfc, bfc, out);
}